// round 16
// baseline (speedup 1.0000x reference)
#include <cuda_runtime.h>
#include <cuda_bf16.h>
#include <cstdint>
#include <math.h>

#define B_SZ 2
#define S_LEN 2048
#define NH 16
#define DH 64
#define DM 1024
#define BH (B_SZ * NH)                 // 32
#define M_ROWS (B_SZ * S_LEN)          // 4096
#define OUT_ELEMS (B_SZ * S_LEN * DM)  // 4,194,304

typedef unsigned short u16;

// ===========================================================================
// Device scratch (allocation-free rule) — separate hi/lo bf16 planes
// ===========================================================================
__device__ __align__(16) u16 g_inH[3][M_ROWS * DM];
__device__ __align__(16) u16 g_inL[3][M_ROWS * DM];
__device__ __align__(16) u16 g_wH[4][DM * DM];     // transposed [N][K]
__device__ __align__(16) u16 g_wL[4][DM * DM];
__device__ __align__(16) u16 g_qH[BH * S_LEN * DH];
__device__ __align__(16) u16 g_qL[BH * S_LEN * DH];
__device__ __align__(16) u16 g_kH[BH * S_LEN * DH];
__device__ __align__(16) u16 g_kL[BH * S_LEN * DH];
__device__ __align__(16) u16 g_vH[BH * DH * S_LEN];  // transposed [bh][dh][s]
__device__ __align__(16) u16 g_vL[BH * DH * S_LEN];
__device__ __align__(16) u16 g_oH[M_ROWS * DM];
__device__ __align__(16) u16 g_oL[M_ROWS * DM];

// ===========================================================================
// Helpers
// ===========================================================================
__device__ __forceinline__ uint32_t pack_split(float x) {
    __nv_bfloat16 h = __float2bfloat16(x);
    __nv_bfloat16 l = __float2bfloat16(x - __bfloat162float(h));
    return (uint32_t)__bfloat16_as_ushort(h) | ((uint32_t)__bfloat16_as_ushort(l) << 16);
}

__device__ __forceinline__ void pack_pair(float x, float y,
                                          uint32_t& hi, uint32_t& lo) {
    uint32_t px = pack_split(x), py = pack_split(y);
    hi = (px & 0xFFFFu) | ((py & 0xFFFFu) << 16);
    lo = (px >> 16) | (py & 0xFFFF0000u);
}

__device__ __forceinline__ uint32_t smem_u32(const void* p) {
    uint32_t a;
    asm("{ .reg .u64 t; cvta.to.shared.u64 t, %1; cvt.u32.u64 %0, t; }"
        : "=r"(a) : "l"(p));
    return a;
}

// streaming store (evict-first) for attn values (never re-read)
__device__ __forceinline__ void stcs2(float* p, float x, float y) {
    asm volatile("st.global.cs.v2.f32 [%0], {%1, %2};"
                 :: "l"(p), "f"(x), "f"(y) : "memory");
}

#define CPA16(s, g) \
    asm volatile("cp.async.cg.shared.global [%0], [%1], 16;" :: "r"(s), "l"(g))
#define CPC() asm volatile("cp.async.commit_group;" ::: "memory")
#define CPW(n) asm volatile("cp.async.wait_group %0;" :: "n"(n) : "memory")

#define LDSM_X4(R0, R1, R2, R3, A) \
    asm volatile("ldmatrix.sync.aligned.m8n8.x4.shared.b16 {%0,%1,%2,%3}, [%4];" \
        : "=r"(R0), "=r"(R1), "=r"(R2), "=r"(R3) : "r"(A))

__device__ __forceinline__ void mma16816(float* c, const uint32_t* a,
                                         uint32_t b0, uint32_t b1) {
    asm volatile(
        "mma.sync.aligned.m16n8k16.row.col.f32.bf16.bf16.f32 "
        "{%0,%1,%2,%3}, {%4,%5,%6,%7}, {%8,%9}, {%0,%1,%2,%3};"
        : "+f"(c[0]), "+f"(c[1]), "+f"(c[2]), "+f"(c[3])
        : "r"(a[0]), "r"(a[1]), "r"(a[2]), "r"(a[3]), "r"(b0), "r"(b1));
}

// ===========================================================================
// cp.async fills: ROWS x KC bf16 plane(s) into smem (row stride KC/2+4 u32)
// ===========================================================================
template <int ROWS, int KC>
__device__ __forceinline__ void fill_async(uint32_t saH, uint32_t saL,
                                           const u16* __restrict__ gh,
                                           const u16* __restrict__ gl,
                                           size_t stride, int tid) {
    constexpr int SEGS = KC * 2 / 16;
    constexpr int SSTR = (KC / 2 + 4) * 4;
    #pragma unroll
    for (int i = 0; i < ROWS * SEGS / 256; i++) {
        int lin = tid + i * 256;
        int r = lin / SEGS, s = lin % SEGS;
        uint32_t so = r * SSTR + s * 16;
        const char* gH = (const char*)(gh + (size_t)r * stride) + s * 16;
        const char* gL = (const char*)(gl + (size_t)r * stride) + s * 16;
        CPA16(saH + so, gH);
        CPA16(saL + so, gL);
    }
}

// single-plane variant (pass-1 K-hi only)
template <int ROWS, int KC>
__device__ __forceinline__ void fill_async1(uint32_t saH,
                                            const u16* __restrict__ gh,
                                            size_t stride, int tid) {
    constexpr int SEGS = KC * 2 / 16;
    constexpr int SSTR = (KC / 2 + 4) * 4;
    #pragma unroll
    for (int i = 0; i < ROWS * SEGS / 256; i++) {
        int lin = tid + i * 256;
        int r = lin / SEGS, s = lin % SEGS;
        uint32_t so = r * SSTR + s * 16;
        const char* gH = (const char*)(gh + (size_t)r * stride) + s * 16;
        CPA16(saH + so, gH);
    }
}

// ===========================================================================
// Warp MMA over one chunk — ldmatrix fragment loads (used by proj/out).
// Three independent sweeps (Ah*Bh, Ah*Bl, Al*Bh) so consecutive MMAs on the
// same accumulator are separated by WM*WN independent ones.
// ===========================================================================
template <int WM, int WN, int KC>
__device__ __forceinline__ void mma_chunk(float acc[WM][WN][4],
                                          uint32_t aH, uint32_t aL,
                                          uint32_t bH, uint32_t bL,
                                          int warp_m, int warp_n, int lane) {
    constexpr int KSTR = KC / 2 + 4;
    const int a_row  = (lane & 15);
    const int a_col  = (lane >> 4) * 4;
    const int b_row  = (lane & 7) + ((lane & 16) >> 1);
    const int b_col  = (lane & 8) ? 4 : 0;
    #pragma unroll
    for (int ks = 0; ks < KC / 16; ks++) {
        uint32_t ah[WM][4], al[WM][4];
        #pragma unroll
        for (int mt = 0; mt < WM; mt++) {
            uint32_t off = ((warp_m + mt * 16 + a_row) * KSTR + ks * 8 + a_col) * 4;
            LDSM_X4(ah[mt][0], ah[mt][1], ah[mt][2], ah[mt][3], aH + off);
            LDSM_X4(al[mt][0], al[mt][1], al[mt][2], al[mt][3], aL + off);
        }
        uint32_t bh[WN][2], bl[WN][2];
        #pragma unroll
        for (int np = 0; np < WN / 2; np++) {
            uint32_t off = ((warp_n + np * 16 + b_row) * KSTR + ks * 8 + b_col) * 4;
            LDSM_X4(bh[2*np][0], bh[2*np][1], bh[2*np+1][0], bh[2*np+1][1], bH + off);
            LDSM_X4(bl[2*np][0], bl[2*np][1], bl[2*np+1][0], bl[2*np+1][1], bL + off);
        }
        #pragma unroll
        for (int nt = 0; nt < WN; nt++)
            #pragma unroll
            for (int mt = 0; mt < WM; mt++)
                mma16816(acc[mt][nt], ah[mt], bh[nt][0], bh[nt][1]);
        #pragma unroll
        for (int nt = 0; nt < WN; nt++)
            #pragma unroll
            for (int mt = 0; mt < WM; mt++)
                mma16816(acc[mt][nt], ah[mt], bl[nt][0], bl[nt][1]);
        #pragma unroll
        for (int nt = 0; nt < WN; nt++)
            #pragma unroll
            for (int mt = 0; mt < WM; mt++)
                mma16816(acc[mt][nt], al[mt], bh[nt][0], bh[nt][1]);
    }
}

// ===========================================================================
// Conversions
// ===========================================================================
__global__ __launch_bounds__(256)
void convert_in(const float* __restrict__ Q, const float* __restrict__ K,
                const float* __restrict__ V, u16* __restrict__ dh,
                u16* __restrict__ dl)
{
    const float* src = (blockIdx.y == 0) ? Q : (blockIdx.y == 1) ? K : V;
    u16* oh = dh + (size_t)blockIdx.y * (M_ROWS * DM);
    u16* ol = dl + (size_t)blockIdx.y * (M_ROWS * DM);
    size_t idx = ((size_t)blockIdx.x * 256 + threadIdx.x) * 8;
    float4 f0 = *(const float4*)(src + idx);
    float4 f1 = *(const float4*)(src + idx + 4);
    uint32_t p[8];
    p[0] = pack_split(f0.x); p[1] = pack_split(f0.y);
    p[2] = pack_split(f0.z); p[3] = pack_split(f0.w);
    p[4] = pack_split(f1.x); p[5] = pack_split(f1.y);
    p[6] = pack_split(f1.z); p[7] = pack_split(f1.w);
    uint4 hv, lv;
    hv.x = (p[0] & 0xFFFFu) | ((p[1] & 0xFFFFu) << 16);
    hv.y = (p[2] & 0xFFFFu) | ((p[3] & 0xFFFFu) << 16);
    hv.z = (p[4] & 0xFFFFu) | ((p[5] & 0xFFFFu) << 16);
    hv.w = (p[6] & 0xFFFFu) | ((p[7] & 0xFFFFu) << 16);
    lv.x = (p[0] >> 16) | (p[1] & 0xFFFF0000u);
    lv.y = (p[2] >> 16) | (p[3] & 0xFFFF0000u);
    lv.z = (p[4] >> 16) | (p[5] & 0xFFFF0000u);
    lv.w = (p[6] >> 16) | (p[7] & 0xFFFF0000u);
    *(uint4*)(oh + idx) = hv;
    *(uint4*)(ol + idx) = lv;
}

__global__ __launch_bounds__(256)
void convert_w(const float* __restrict__ Wq, const float* __restrict__ Wk,
               const float* __restrict__ Wv, const float* __restrict__ Wo,
               u16* __restrict__ dh, u16* __restrict__ dl)
{
    __shared__ float sm[64][65];
    const float* W = (blockIdx.z == 0) ? Wq : (blockIdx.z == 1) ? Wk :
                     (blockIdx.z == 2) ? Wv : Wo;
    u16* oh = dh + (size_t)blockIdx.z * (DM * DM);
    u16* ol = dl + (size_t)blockIdx.z * (DM * DM);
    const int k0 = blockIdx.x * 64;
    const int n0 = blockIdx.y * 64;
    const int tid = threadIdx.x;

    #pragma unroll
    for (int i = 0; i < 4; i++) {
        int lin = tid + i * 256;
        int r = lin >> 4, q = lin & 15;
        float4 f = *(const float4*)(W + (size_t)(k0 + r) * DM + n0 + q * 4);
        sm[r][q * 4 + 0] = f.x; sm[r][q * 4 + 1] = f.y;
        sm[r][q * 4 + 2] = f.z; sm[r][q * 4 + 3] = f.w;
    }
    __syncthreads();
    #pragma unroll
    for (int i = 0; i < 4; i++) {
        int lin = tid + i * 256;
        int r = lin >> 4, q = lin & 15;
        uint32_t h0, l0, h1, l1;
        pack_pair(sm[q * 4 + 0][r], sm[q * 4 + 1][r], h0, l0);
        pack_pair(sm[q * 4 + 2][r], sm[q * 4 + 3][r], h1, l1);
        size_t base = (size_t)(n0 + r) * DM + k0 + q * 4;
        *(uint2*)(oh + base) = make_uint2(h0, h1);
        *(uint2*)(ol + base) = make_uint2(l0, l1);
    }
}

// ===========================================================================
// QKV projection: 128x128 CTA, 8 warps (2m x 4n, warp 64x32), KC=32,
// cp.async double-buffered, 2 CTAs/SM.
// ===========================================================================
__global__ __launch_bounds__(256, 2)
void proj_mma(const u16* __restrict__ inH, const u16* __restrict__ inL,
              const u16* __restrict__ wH, const u16* __restrict__ wL,
              const float* __restrict__ bq, const float* __restrict__ bk,
              const float* __restrict__ bv,
              u16* __restrict__ qH, u16* __restrict__ qL,
              u16* __restrict__ kH, u16* __restrict__ kL,
              u16* __restrict__ vH, u16* __restrict__ vL)
{
    constexpr int KC = 32, KSTR = KC / 2 + 4;  // 20 u32
    constexpr int PL = 128 * KSTR;             // 2560 u32
    constexpr int BUF = 4 * PL;
    extern __shared__ uint32_t sm[];
    uint32_t sa = smem_u32(sm);

    const int z = blockIdx.z;
    const u16* A_H = inH + (size_t)z * (M_ROWS * DM);
    const u16* A_L = inL + (size_t)z * (M_ROWS * DM);
    const u16* W_H = wH + (size_t)z * (DM * DM);
    const u16* W_L = wL + (size_t)z * (DM * DM);
    const float* bias = (z == 0) ? bq : (z == 1) ? bk : bv;

    const int tid = threadIdx.x;
    const int wid = tid >> 5, lane = tid & 31;
    const int bm = blockIdx.x * 128;
    const int bn = blockIdx.y * 128;
    const int warp_m = (wid >> 2) * 64;
    const int warp_n = (wid & 3) * 32;

    float acc[4][4][4] = {};

    fill_async<128, KC>(sa, sa + PL * 4, A_H + (size_t)bm * DM, A_L + (size_t)bm * DM, DM, tid);
    fill_async<128, KC>(sa + 2 * PL * 4, sa + 3 * PL * 4, W_H + (size_t)bn * DM, W_L + (size_t)bn * DM, DM, tid);
    CPC();

    #pragma unroll 1
    for (int c = 0; c < DM / KC; c++) {
        if (c + 1 < DM / KC) {
            uint32_t b = sa + ((c + 1) & 1) * BUF * 4;
            fill_async<128, KC>(b, b + PL * 4,
                                A_H + (size_t)bm * DM + (c + 1) * KC,
                                A_L + (size_t)bm * DM + (c + 1) * KC, DM, tid);
            fill_async<128, KC>(b + 2 * PL * 4, b + 3 * PL * 4,
                                W_H + (size_t)bn * DM + (c + 1) * KC,
                                W_L + (size_t)bn * DM + (c + 1) * KC, DM, tid);
            CPC();
            CPW(1);
        } else {
            CPW(0);
        }
        __syncthreads();
        uint32_t ba = sa + (c & 1) * BUF * 4;
        mma_chunk<4, 4, KC>(acc, ba, ba + PL * 4, ba + 2 * PL * 4, ba + 3 * PL * 4,
                            warp_m, warp_n, lane);
        __syncthreads();
    }

    const int lr = lane >> 2, lc = (lane & 3) * 2;
    #pragma unroll
    for (int mt = 0; mt < 4; mt++) {
        #pragma unroll
        for (int nt = 0; nt < 4; nt++) {
            int col = bn + warp_n + nt * 8 + lc;
            float b0 = bias[col], b1 = bias[col + 1];
            int h = col >> 6, dh = col & 63;
            #pragma unroll
            for (int half = 0; half < 2; half++) {
                int r = bm + warp_m + mt * 16 + lr + half * 8;
                float v0 = acc[mt][nt][half * 2 + 0] + b0;
                float v1 = acc[mt][nt][half * 2 + 1] + b1;
                int b = r >> 11, s = r & (S_LEN - 1);
                int bh = b * NH + h;
                uint32_t p0 = pack_split(v0), p1 = pack_split(v1);
                if (z == 2) {
                    size_t t0 = ((size_t)bh * DH + dh) * S_LEN + s;
                    size_t t1 = ((size_t)bh * DH + dh + 1) * S_LEN + s;
                    vH[t0] = (u16)p0; vL[t0] = (u16)(p0 >> 16);
                    vH[t1] = (u16)p1; vL[t1] = (u16)(p1 >> 16);
                } else {
                    u16* dH = (z == 0) ? qH : kH;
                    u16* dL = (z == 0) ? qL : kL;
                    size_t base = ((size_t)bh * S_LEN + s) * DH + dh;
                    *(uint32_t*)(dH + base) = (p0 & 0xFFFFu) | ((p1 & 0xFFFFu) << 16);
                    *(uint32_t*)(dL + base) = (p0 >> 16) | (p1 & 0xFFFF0000u);
                }
            }
        }
    }
}

// ===========================================================================
// Fused attention: scores + softmax + AV, two passes over K.
// Pass 1 (S only, M=0): hi-plane scores, 128-row K tiles.
// Pass 2: exact 3-MMA QK + 3-MMA PV (independent sweeps), streaming attn.
// ===========================================================================
__global__ __launch_bounds__(256, 2)
void fused_attn(const u16* __restrict__ qH, const u16* __restrict__ qL,
                const u16* __restrict__ kH, const u16* __restrict__ kL,
                const u16* __restrict__ vH, const u16* __restrict__ vL,
                float* __restrict__ attn,
                u16* __restrict__ oH, u16* __restrict__ oL, float scale)
{
    constexpr int KSTR = 36;               // 64/2 + 4
    constexpr int QPL = 128 * KSTR;        // Q plane (u32)
    constexpr int TPL = 64 * KSTR;         // 64-row tile plane (u32)
    extern __shared__ uint32_t sm[];
    uint32_t sa = smem_u32(sm);
    const uint32_t kbase = sa;                      // K region: 4*TPL u32 (36KB)
    const uint32_t qvbase = sa + 4 * TPL * 4;       // Q planes / V ring (36KB)
    const uint32_t oQH = qvbase;
    const uint32_t oQL = qvbase + QPL * 4;
    const uint32_t vbase = qvbase;                  // V ring overlays Q

    const int bh = blockIdx.z;
    const int bb = bh >> 4, hh = bh & 15;
    const int tid = threadIdx.x, wid = tid >> 5, lane = tid & 31;
    const int bm = blockIdx.x * 128;
    const int wm = wid * 16;
    const size_t qoff = ((size_t)bh * S_LEN + bm) * DH;
    const u16* kbH = kH + (size_t)bh * S_LEN * DH;
    const u16* kbL = kL + (size_t)bh * S_LEN * DH;
    const u16* vbH = vH + (size_t)bh * DH * S_LEN;
    const u16* vbL = vL + (size_t)bh * DH * S_LEN;
    float* ab = attn + (size_t)bh * S_LEN * S_LEN;

    const int a_row = lane & 15;
    const int a_col = (lane >> 4) * 4;
    const int b_row = (lane & 7) + ((lane & 16) >> 1);
    const int b_col = (lane & 8) ? 4 : 0;
    const int lr = lane >> 2, lg = lane & 3;

    // prologue: Q (both planes) + K-hi tile 0 (128 rows)
    fill_async<128, 64>(oQH, oQL, qH + qoff, qL + qoff, DH, tid);
    fill_async1<128, 64>(kbase, kbH, DH, tid);
    CPC(); CPW(0);
    __syncthreads();

    // Q fragments: register-resident for both passes
    uint32_t qfh[4][4], qfl[4][4];
    #pragma unroll
    for (int ks = 0; ks < 4; ks++) {
        uint32_t off = ((wm + a_row) * KSTR + ks * 8 + a_col) * 4;
        LDSM_X4(qfh[ks][0], qfh[ks][1], qfh[ks][2], qfh[ks][3], oQH + off);
        LDSM_X4(qfl[ks][0], qfl[ks][1], qfl[ks][2], qfl[ks][3], oQL + off);
    }
    __syncthreads();   // Q region free after this point (V may overwrite)

    float S0 = 0.f, S1 = 0.f;

    // ---------------- pass 1: S only, 128-row K-hi tiles ----------------
    #pragma unroll 1
    for (int t = 0; t < 16; t++) {
        if (t + 1 < 16) {
            uint32_t kb = kbase + ((t + 1) & 1) * 2 * TPL * 4;
            fill_async1<128, 64>(kb, kbH + (size_t)(t + 1) * 128 * DH, DH, tid);
            CPC(); CPW(1);
        } else CPW(0);
        __syncthreads();

        uint32_t kh_ = kbase + (t & 1) * 2 * TPL * 4;
        #pragma unroll
        for (int half = 0; half < 2; half++) {
            float acc[8][4] = {};
            #pragma unroll
            for (int ks = 0; ks < 4; ks++) {
                uint32_t bhf[8][2];
                #pragma unroll
                for (int np = 0; np < 4; np++) {
                    uint32_t off = ((half * 64 + np * 16 + b_row) * KSTR + ks * 8 + b_col) * 4;
                    LDSM_X4(bhf[2*np][0], bhf[2*np][1], bhf[2*np+1][0], bhf[2*np+1][1], kh_ + off);
                }
                #pragma unroll
                for (int nt = 0; nt < 8; nt++)
                    mma16816(acc[nt], qfh[ks], bhf[nt][0], bhf[nt][1]);
            }
            float s0t = 0.f, s1t = 0.f;
            #pragma unroll
            for (int nt = 0; nt < 8; nt++) {
                s0t += __expf(acc[nt][0] * scale) + __expf(acc[nt][1] * scale);
                s1t += __expf(acc[nt][2] * scale) + __expf(acc[nt][3] * scale);
            }
            S0 += s0t;
            S1 += s1t;
        }
        __syncthreads();
    }
    S0 += __shfl_xor_sync(0xffffffffu, S0, 1);
    S0 += __shfl_xor_sync(0xffffffffu, S0, 2);
    S1 += __shfl_xor_sync(0xffffffffu, S1, 1);
    S1 += __shfl_xor_sync(0xffffffffu, S1, 2);
    const float inv0 = 1.0f / S0, inv1 = 1.0f / S1;

    // ---------------- pass 2: exact scores, attn write + P@V ----------------
    fill_async<64, 64>(kbase, kbase + TPL * 4, kbH, kbL, DH, tid);
    fill_async<64, 64>(vbase, vbase + TPL * 4, vbH, vbL, S_LEN, tid);
    CPC();

    float acco[8][4] = {};
    const int r0 = bm + wm + lr;
    const int r1 = r0 + 8;

    #pragma unroll 1
    for (int t = 0; t < 32; t++) {
        if (t + 1 < 32) {
            uint32_t kb = kbase + ((t + 1) & 1) * 2 * TPL * 4;
            uint32_t vb = vbase + ((t + 1) & 1) * 2 * TPL * 4;
            fill_async<64, 64>(kb, kb + TPL * 4,
                               kbH + (size_t)(t + 1) * 64 * DH,
                               kbL + (size_t)(t + 1) * 64 * DH, DH, tid);
            fill_async<64, 64>(vb, vb + TPL * 4,
                               vbH + (size_t)(t + 1) * 64,
                               vbL + (size_t)(t + 1) * 64, S_LEN, tid);
            CPC(); CPW(1);
        } else CPW(0);
        __syncthreads();

        uint32_t kh_ = kbase + (t & 1) * 2 * TPL * 4;
        uint32_t kl_ = kh_ + TPL * 4;
        float acc[8][4] = {};
        #pragma unroll
        for (int ks = 0; ks < 4; ks++) {
            uint32_t bhf[8][2], blf[8][2];
            #pragma unroll
            for (int np = 0; np < 4; np++) {
                uint32_t off = ((np * 16 + b_row) * KSTR + ks * 8 + b_col) * 4;
                LDSM_X4(bhf[2*np][0], bhf[2*np][1], bhf[2*np+1][0], bhf[2*np+1][1], kh_ + off);
                LDSM_X4(blf[2*np][0], blf[2*np][1], blf[2*np+1][0], blf[2*np+1][1], kl_ + off);
            }
            #pragma unroll
            for (int nt = 0; nt < 8; nt++)
                mma16816(acc[nt], qfh[ks], bhf[nt][0], bhf[nt][1]);
            #pragma unroll
            for (int nt = 0; nt < 8; nt++)
                mma16816(acc[nt], qfh[ks], blf[nt][0], blf[nt][1]);
            #pragma unroll
            for (int nt = 0; nt < 8; nt++)
                mma16816(acc[nt], qfl[ks], bhf[nt][0], bhf[nt][1]);
        }
        float pA[8][2], pB[8][2];
        #pragma unroll
        for (int nt = 0; nt < 8; nt++) {
            pA[nt][0] = __expf(acc[nt][0] * scale) * inv0;
            pA[nt][1] = __expf(acc[nt][1] * scale) * inv0;
            pB[nt][0] = __expf(acc[nt][2] * scale) * inv1;
            pB[nt][1] = __expf(acc[nt][3] * scale) * inv1;
            int col = t * 64 + nt * 8 + 2 * lg;
            stcs2(ab + (size_t)r0 * S_LEN + col, pA[nt][0], pA[nt][1]);
            stcs2(ab + (size_t)r1 * S_LEN + col, pB[nt][0], pB[nt][1]);
        }
        uint32_t vh_ = vbase + (t & 1) * 2 * TPL * 4;
        uint32_t vl_ = vh_ + TPL * 4;
        #pragma unroll
        for (int ks = 0; ks < 4; ks++) {
            uint32_t ah[4], al[4];
            pack_pair(pA[2*ks][0],   pA[2*ks][1],   ah[0], al[0]);
            pack_pair(pB[2*ks][0],   pB[2*ks][1],   ah[1], al[1]);
            pack_pair(pA[2*ks+1][0], pA[2*ks+1][1], ah[2], al[2]);
            pack_pair(pB[2*ks+1][0], pB[2*ks+1][1], ah[3], al[3]);
            uint32_t bhf[8][2], blf[8][2];
            #pragma unroll
            for (int np = 0; np < 4; np++) {
                uint32_t off = ((np * 16 + b_row) * KSTR + ks * 8 + b_col) * 4;
                LDSM_X4(bhf[2*np][0], bhf[2*np][1], bhf[2*np+1][0], bhf[2*np+1][1], vh_ + off);
                LDSM_X4(blf[2*np][0], blf[2*np][1], blf[2*np+1][0], blf[2*np+1][1], vl_ + off);
            }
            #pragma unroll
            for (int nt = 0; nt < 8; nt++)
                mma16816(acco[nt], ah, bhf[nt][0], bhf[nt][1]);
            #pragma unroll
            for (int nt = 0; nt < 8; nt++)
                mma16816(acco[nt], ah, blf[nt][0], blf[nt][1]);
            #pragma unroll
            for (int nt = 0; nt < 8; nt++)
                mma16816(acco[nt], al, bhf[nt][0], bhf[nt][1]);
        }
        __syncthreads();
    }

    // epilogue: o -> packed split planes, concat-head layout
    #pragma unroll
    for (int nt = 0; nt < 8; nt++) {
        int col = nt * 8 + 2 * lg;
        size_t base0 = ((size_t)bb * S_LEN + r0) * DM + hh * DH + col;
        size_t base1 = ((size_t)bb * S_LEN + r1) * DM + hh * DH + col;
        uint32_t h0, l0, h1, l1;
        pack_pair(acco[nt][0], acco[nt][1], h0, l0);
        pack_pair(acco[nt][2], acco[nt][3], h1, l1);
        *(uint32_t*)(oH + base0) = h0;
        *(uint32_t*)(oL + base0) = l0;
        *(uint32_t*)(oH + base1) = h1;
        *(uint32_t*)(oL + base1) = l1;
    }
}

// ===========================================================================
// Output projection: KC=32 double-buffered, 2 CTAs/SM, fp32 out.
// ===========================================================================
__global__ __launch_bounds__(256, 2)
void out_mma(const u16* __restrict__ aH, const u16* __restrict__ aL,
             const u16* __restrict__ wH, const u16* __restrict__ wL,
             const float* __restrict__ bo, float* __restrict__ out)
{
    constexpr int KC = 32, KSTR = KC / 2 + 4;
    constexpr int PL = 128 * KSTR;
    constexpr int BUF = 4 * PL;
    extern __shared__ uint32_t sm[];
    uint32_t sa = smem_u32(sm);

    const int tid = threadIdx.x;
    const int wid = tid >> 5, lane = tid & 31;
    const int bm = blockIdx.x * 128;
    const int bn = blockIdx.y * 128;
    const int warp_m = (wid >> 2) * 64;
    const int warp_n = (wid & 3) * 32;

    float acc[4][4][4] = {};

    fill_async<128, KC>(sa, sa + PL * 4, aH + (size_t)bm * DM, aL + (size_t)bm * DM, DM, tid);
    fill_async<128, KC>(sa + 2 * PL * 4, sa + 3 * PL * 4, wH + (size_t)bn * DM, wL + (size_t)bn * DM, DM, tid);
    CPC();

    #pragma unroll 1
    for (int c = 0; c < DM / KC; c++) {
        if (c + 1 < DM / KC) {
            uint32_t b = sa + ((c + 1) & 1) * BUF * 4;
            fill_async<128, KC>(b, b + PL * 4,
                                aH + (size_t)bm * DM + (c + 1) * KC,
                                aL + (size_t)bm * DM + (c + 1) * KC, DM, tid);
            fill_async<128, KC>(b + 2 * PL * 4, b + 3 * PL * 4,
                                wH + (size_t)bn * DM + (c + 1) * KC,
                                wL + (size_t)bn * DM + (c + 1) * KC, DM, tid);
            CPC();
            CPW(1);
        } else {
            CPW(0);
        }
        __syncthreads();
        uint32_t ba = sa + (c & 1) * BUF * 4;
        mma_chunk<4, 4, KC>(acc, ba, ba + PL * 4, ba + 2 * PL * 4, ba + 3 * PL * 4,
                            warp_m, warp_n, lane);
        __syncthreads();
    }

    const int lr = lane >> 2, lc = (lane & 3) * 2;
    #pragma unroll
    for (int mt = 0; mt < 4; mt++) {
        #pragma unroll
        for (int nt = 0; nt < 4; nt++) {
            int col = bn + warp_n + nt * 8 + lc;
            float b0 = bo[col], b1 = bo[col + 1];
            #pragma unroll
            for (int half = 0; half < 2; half++) {
                int r = bm + warp_m + mt * 16 + lr + half * 8;
                *(float2*)(out + (size_t)r * DM + col) =
                    make_float2(acc[mt][nt][half * 2 + 0] + b0,
                                acc[mt][nt][half * 2 + 1] + b1);
            }
        }
    }
}

// ===========================================================================
// Launch
// ===========================================================================
extern "C" void kernel_launch(void* const* d_in, const int* in_sizes, int n_in,
                              void* d_out, int out_size)
{
    const float* Q  = (const float*)d_in[0];
    const float* K  = (const float*)d_in[1];
    const float* V  = (const float*)d_in[2];
    const float* Wq = (const float*)d_in[3];
    const float* bq = (const float*)d_in[4];
    const float* Wk = (const float*)d_in[5];
    const float* bk = (const float*)d_in[6];
    const float* Wv = (const float*)d_in[7];
    const float* bv = (const float*)d_in[8];
    const float* Wo = (const float*)d_in[9];
    const float* bo = (const float*)d_in[10];

    float* out  = (float*)d_out;
    float* attn = out + OUT_ELEMS;

    u16 *inH, *inL, *wH, *wL, *qH, *qL, *kH, *kL, *vH, *vL, *oH, *oL;
    cudaGetSymbolAddress((void**)&inH, g_inH);
    cudaGetSymbolAddress((void**)&inL, g_inL);
    cudaGetSymbolAddress((void**)&wH, g_wH);
    cudaGetSymbolAddress((void**)&wL, g_wL);
    cudaGetSymbolAddress((void**)&qH, g_qH);
    cudaGetSymbolAddress((void**)&qL, g_qL);
    cudaGetSymbolAddress((void**)&kH, g_kH);
    cudaGetSymbolAddress((void**)&kL, g_kL);
    cudaGetSymbolAddress((void**)&vH, g_vH);
    cudaGetSymbolAddress((void**)&vL, g_vL);
    cudaGetSymbolAddress((void**)&oH, g_oH);
    cudaGetSymbolAddress((void**)&oL, g_oL);

    const int KSTR32 = 32 / 2 + 4;                            // 20
    const int SM_PROJ = 2 * 4 * 128 * KSTR32 * 4;             // 81920
    const int SM_FA   = (4 * 64 + 2 * 128) * 36 * 4;          // 73728
    cudaFuncSetAttribute(proj_mma, cudaFuncAttributeMaxDynamicSharedMemorySize, SM_PROJ);
    cudaFuncSetAttribute(out_mma, cudaFuncAttributeMaxDynamicSharedMemorySize, SM_PROJ);
    cudaFuncSetAttribute(fused_attn, cudaFuncAttributeMaxDynamicSharedMemorySize, SM_FA);

    convert_in<<<dim3(M_ROWS * DM / 8 / 256, 3), 256>>>(Q, K, V, inH, inL);
    convert_w<<<dim3(DM / 64, DM / 64, 4), 256>>>(Wq, Wk, Wv, Wo, wH, wL);

    proj_mma<<<dim3(M_ROWS / 128, DM / 128, 3), 256, SM_PROJ>>>(
        inH, inL, wH, wL, bq, bk, bv, qH, qL, kH, kL, vH, vL);

    fused_attn<<<dim3(S_LEN / 128, 1, BH), 256, SM_FA>>>(
        qH, qL, kH, kL, vH, vL, attn, oH, oL, 0.125f);

    out_mma<<<dim3(M_ROWS / 128, DM / 128), 256, SM_PROJ>>>(
        oH, oL, wH + 3 * (size_t)(DM * DM), wL + 3 * (size_t)(DM * DM), bo, out);
}

// round 17
// speedup vs baseline: 1.0287x; 1.0287x over previous
#include <cuda_runtime.h>
#include <cuda_bf16.h>
#include <cstdint>
#include <math.h>

#define B_SZ 2
#define S_LEN 2048
#define NH 16
#define DH 64
#define DM 1024
#define BH (B_SZ * NH)                 // 32
#define M_ROWS (B_SZ * S_LEN)          // 4096
#define OUT_ELEMS (B_SZ * S_LEN * DM)  // 4,194,304

typedef unsigned short u16;

// ===========================================================================
// Device scratch (allocation-free rule) — separate hi/lo bf16 planes
// ===========================================================================
__device__ __align__(16) u16 g_inH[3][M_ROWS * DM];
__device__ __align__(16) u16 g_inL[3][M_ROWS * DM];
__device__ __align__(16) u16 g_wH[4][DM * DM];     // transposed [N][K]
__device__ __align__(16) u16 g_wL[4][DM * DM];
__device__ __align__(16) u16 g_qH[BH * S_LEN * DH];
__device__ __align__(16) u16 g_qL[BH * S_LEN * DH];
__device__ __align__(16) u16 g_kH[BH * S_LEN * DH];
__device__ __align__(16) u16 g_kL[BH * S_LEN * DH];
__device__ __align__(16) u16 g_vH[BH * DH * S_LEN];  // transposed [bh][dh][s]
__device__ __align__(16) u16 g_vL[BH * DH * S_LEN];
__device__ __align__(16) u16 g_oH[M_ROWS * DM];
__device__ __align__(16) u16 g_oL[M_ROWS * DM];

// ===========================================================================
// Helpers
// ===========================================================================
__device__ __forceinline__ uint32_t pack_split(float x) {
    __nv_bfloat16 h = __float2bfloat16(x);
    __nv_bfloat16 l = __float2bfloat16(x - __bfloat162float(h));
    return (uint32_t)__bfloat16_as_ushort(h) | ((uint32_t)__bfloat16_as_ushort(l) << 16);
}

__device__ __forceinline__ void pack_pair(float x, float y,
                                          uint32_t& hi, uint32_t& lo) {
    uint32_t px = pack_split(x), py = pack_split(y);
    hi = (px & 0xFFFFu) | ((py & 0xFFFFu) << 16);
    lo = (px >> 16) | (py & 0xFFFF0000u);
}

__device__ __forceinline__ uint32_t smem_u32(const void* p) {
    uint32_t a;
    asm("{ .reg .u64 t; cvta.to.shared.u64 t, %1; cvt.u32.u64 %0, t; }"
        : "=r"(a) : "l"(p));
    return a;
}

// streaming store (evict-first) for attn values (never re-read)
__device__ __forceinline__ void stcs2(float* p, float x, float y) {
    asm volatile("st.global.cs.v2.f32 [%0], {%1, %2};"
                 :: "l"(p), "f"(x), "f"(y) : "memory");
}

#define CPA16(s, g) \
    asm volatile("cp.async.cg.shared.global [%0], [%1], 16;" :: "r"(s), "l"(g))
#define CPC() asm volatile("cp.async.commit_group;" ::: "memory")
#define CPW(n) asm volatile("cp.async.wait_group %0;" :: "n"(n) : "memory")

#define LDSM_X4(R0, R1, R2, R3, A) \
    asm volatile("ldmatrix.sync.aligned.m8n8.x4.shared.b16 {%0,%1,%2,%3}, [%4];" \
        : "=r"(R0), "=r"(R1), "=r"(R2), "=r"(R3) : "r"(A))

__device__ __forceinline__ void mma16816(float* c, const uint32_t* a,
                                         uint32_t b0, uint32_t b1) {
    asm volatile(
        "mma.sync.aligned.m16n8k16.row.col.f32.bf16.bf16.f32 "
        "{%0,%1,%2,%3}, {%4,%5,%6,%7}, {%8,%9}, {%0,%1,%2,%3};"
        : "+f"(c[0]), "+f"(c[1]), "+f"(c[2]), "+f"(c[3])
        : "r"(a[0]), "r"(a[1]), "r"(a[2]), "r"(a[3]), "r"(b0), "r"(b1));
}

// ===========================================================================
// cp.async fills: ROWS x KC bf16 plane(s) into smem (row stride KC/2+4 u32)
// ===========================================================================
template <int ROWS, int KC>
__device__ __forceinline__ void fill_async(uint32_t saH, uint32_t saL,
                                           const u16* __restrict__ gh,
                                           const u16* __restrict__ gl,
                                           size_t stride, int tid) {
    constexpr int SEGS = KC * 2 / 16;
    constexpr int SSTR = (KC / 2 + 4) * 4;
    #pragma unroll
    for (int i = 0; i < ROWS * SEGS / 256; i++) {
        int lin = tid + i * 256;
        int r = lin / SEGS, s = lin % SEGS;
        uint32_t so = r * SSTR + s * 16;
        const char* gH = (const char*)(gh + (size_t)r * stride) + s * 16;
        const char* gL = (const char*)(gl + (size_t)r * stride) + s * 16;
        CPA16(saH + so, gH);
        CPA16(saL + so, gL);
    }
}

// single-plane variant (pass-1 K-hi only)
template <int ROWS, int KC>
__device__ __forceinline__ void fill_async1(uint32_t saH,
                                            const u16* __restrict__ gh,
                                            size_t stride, int tid) {
    constexpr int SEGS = KC * 2 / 16;
    constexpr int SSTR = (KC / 2 + 4) * 4;
    #pragma unroll
    for (int i = 0; i < ROWS * SEGS / 256; i++) {
        int lin = tid + i * 256;
        int r = lin / SEGS, s = lin % SEGS;
        uint32_t so = r * SSTR + s * 16;
        const char* gH = (const char*)(gh + (size_t)r * stride) + s * 16;
        CPA16(saH + so, gH);
    }
}

// ===========================================================================
// Warp MMA over one chunk (proj/out): three independent sweeps — measured
// faster for the 16-accumulator GEMM kernels (R16 evidence).
// ===========================================================================
template <int WM, int WN, int KC>
__device__ __forceinline__ void mma_chunk(float acc[WM][WN][4],
                                          uint32_t aH, uint32_t aL,
                                          uint32_t bH, uint32_t bL,
                                          int warp_m, int warp_n, int lane) {
    constexpr int KSTR = KC / 2 + 4;
    const int a_row  = (lane & 15);
    const int a_col  = (lane >> 4) * 4;
    const int b_row  = (lane & 7) + ((lane & 16) >> 1);
    const int b_col  = (lane & 8) ? 4 : 0;
    #pragma unroll
    for (int ks = 0; ks < KC / 16; ks++) {
        uint32_t ah[WM][4], al[WM][4];
        #pragma unroll
        for (int mt = 0; mt < WM; mt++) {
            uint32_t off = ((warp_m + mt * 16 + a_row) * KSTR + ks * 8 + a_col) * 4;
            LDSM_X4(ah[mt][0], ah[mt][1], ah[mt][2], ah[mt][3], aH + off);
            LDSM_X4(al[mt][0], al[mt][1], al[mt][2], al[mt][3], aL + off);
        }
        uint32_t bh[WN][2], bl[WN][2];
        #pragma unroll
        for (int np = 0; np < WN / 2; np++) {
            uint32_t off = ((warp_n + np * 16 + b_row) * KSTR + ks * 8 + b_col) * 4;
            LDSM_X4(bh[2*np][0], bh[2*np][1], bh[2*np+1][0], bh[2*np+1][1], bH + off);
            LDSM_X4(bl[2*np][0], bl[2*np][1], bl[2*np+1][0], bl[2*np+1][1], bL + off);
        }
        #pragma unroll
        for (int nt = 0; nt < WN; nt++)
            #pragma unroll
            for (int mt = 0; mt < WM; mt++)
                mma16816(acc[mt][nt], ah[mt], bh[nt][0], bh[nt][1]);
        #pragma unroll
        for (int nt = 0; nt < WN; nt++)
            #pragma unroll
            for (int mt = 0; mt < WM; mt++)
                mma16816(acc[mt][nt], ah[mt], bl[nt][0], bl[nt][1]);
        #pragma unroll
        for (int nt = 0; nt < WN; nt++)
            #pragma unroll
            for (int mt = 0; mt < WM; mt++)
                mma16816(acc[mt][nt], al[mt], bh[nt][0], bh[nt][1]);
    }
}

// ===========================================================================
// Conversions
// ===========================================================================
__global__ __launch_bounds__(256)
void convert_in(const float* __restrict__ Q, const float* __restrict__ K,
                const float* __restrict__ V, u16* __restrict__ dh,
                u16* __restrict__ dl)
{
    const float* src = (blockIdx.y == 0) ? Q : (blockIdx.y == 1) ? K : V;
    u16* oh = dh + (size_t)blockIdx.y * (M_ROWS * DM);
    u16* ol = dl + (size_t)blockIdx.y * (M_ROWS * DM);
    size_t idx = ((size_t)blockIdx.x * 256 + threadIdx.x) * 8;
    float4 f0 = *(const float4*)(src + idx);
    float4 f1 = *(const float4*)(src + idx + 4);
    uint32_t p[8];
    p[0] = pack_split(f0.x); p[1] = pack_split(f0.y);
    p[2] = pack_split(f0.z); p[3] = pack_split(f0.w);
    p[4] = pack_split(f1.x); p[5] = pack_split(f1.y);
    p[6] = pack_split(f1.z); p[7] = pack_split(f1.w);
    uint4 hv, lv;
    hv.x = (p[0] & 0xFFFFu) | ((p[1] & 0xFFFFu) << 16);
    hv.y = (p[2] & 0xFFFFu) | ((p[3] & 0xFFFFu) << 16);
    hv.z = (p[4] & 0xFFFFu) | ((p[5] & 0xFFFFu) << 16);
    hv.w = (p[6] & 0xFFFFu) | ((p[7] & 0xFFFFu) << 16);
    lv.x = (p[0] >> 16) | (p[1] & 0xFFFF0000u);
    lv.y = (p[2] >> 16) | (p[3] & 0xFFFF0000u);
    lv.z = (p[4] >> 16) | (p[5] & 0xFFFF0000u);
    lv.w = (p[6] >> 16) | (p[7] & 0xFFFF0000u);
    *(uint4*)(oh + idx) = hv;
    *(uint4*)(ol + idx) = lv;
}

__global__ __launch_bounds__(256)
void convert_w(const float* __restrict__ Wq, const float* __restrict__ Wk,
               const float* __restrict__ Wv, const float* __restrict__ Wo,
               u16* __restrict__ dh, u16* __restrict__ dl)
{
    __shared__ float sm[64][65];
    const float* W = (blockIdx.z == 0) ? Wq : (blockIdx.z == 1) ? Wk :
                     (blockIdx.z == 2) ? Wv : Wo;
    u16* oh = dh + (size_t)blockIdx.z * (DM * DM);
    u16* ol = dl + (size_t)blockIdx.z * (DM * DM);
    const int k0 = blockIdx.x * 64;
    const int n0 = blockIdx.y * 64;
    const int tid = threadIdx.x;

    #pragma unroll
    for (int i = 0; i < 4; i++) {
        int lin = tid + i * 256;
        int r = lin >> 4, q = lin & 15;
        float4 f = *(const float4*)(W + (size_t)(k0 + r) * DM + n0 + q * 4);
        sm[r][q * 4 + 0] = f.x; sm[r][q * 4 + 1] = f.y;
        sm[r][q * 4 + 2] = f.z; sm[r][q * 4 + 3] = f.w;
    }
    __syncthreads();
    #pragma unroll
    for (int i = 0; i < 4; i++) {
        int lin = tid + i * 256;
        int r = lin >> 4, q = lin & 15;
        uint32_t h0, l0, h1, l1;
        pack_pair(sm[q * 4 + 0][r], sm[q * 4 + 1][r], h0, l0);
        pack_pair(sm[q * 4 + 2][r], sm[q * 4 + 3][r], h1, l1);
        size_t base = (size_t)(n0 + r) * DM + k0 + q * 4;
        *(uint2*)(oh + base) = make_uint2(h0, h1);
        *(uint2*)(ol + base) = make_uint2(l0, l1);
    }
}

// ===========================================================================
// QKV projection: 128x128 CTA, 8 warps (2m x 4n, warp 64x32), KC=32,
// cp.async double-buffered, 2 CTAs/SM.
// ===========================================================================
__global__ __launch_bounds__(256, 2)
void proj_mma(const u16* __restrict__ inH, const u16* __restrict__ inL,
              const u16* __restrict__ wH, const u16* __restrict__ wL,
              const float* __restrict__ bq, const float* __restrict__ bk,
              const float* __restrict__ bv,
              u16* __restrict__ qH, u16* __restrict__ qL,
              u16* __restrict__ kH, u16* __restrict__ kL,
              u16* __restrict__ vH, u16* __restrict__ vL)
{
    constexpr int KC = 32, KSTR = KC / 2 + 4;  // 20 u32
    constexpr int PL = 128 * KSTR;             // 2560 u32
    constexpr int BUF = 4 * PL;
    extern __shared__ uint32_t sm[];
    uint32_t sa = smem_u32(sm);

    const int z = blockIdx.z;
    const u16* A_H = inH + (size_t)z * (M_ROWS * DM);
    const u16* A_L = inL + (size_t)z * (M_ROWS * DM);
    const u16* W_H = wH + (size_t)z * (DM * DM);
    const u16* W_L = wL + (size_t)z * (DM * DM);
    const float* bias = (z == 0) ? bq : (z == 1) ? bk : bv;

    const int tid = threadIdx.x;
    const int wid = tid >> 5, lane = tid & 31;
    const int bm = blockIdx.x * 128;
    const int bn = blockIdx.y * 128;
    const int warp_m = (wid >> 2) * 64;
    const int warp_n = (wid & 3) * 32;

    float acc[4][4][4] = {};

    fill_async<128, KC>(sa, sa + PL * 4, A_H + (size_t)bm * DM, A_L + (size_t)bm * DM, DM, tid);
    fill_async<128, KC>(sa + 2 * PL * 4, sa + 3 * PL * 4, W_H + (size_t)bn * DM, W_L + (size_t)bn * DM, DM, tid);
    CPC();

    #pragma unroll 1
    for (int c = 0; c < DM / KC; c++) {
        if (c + 1 < DM / KC) {
            uint32_t b = sa + ((c + 1) & 1) * BUF * 4;
            fill_async<128, KC>(b, b + PL * 4,
                                A_H + (size_t)bm * DM + (c + 1) * KC,
                                A_L + (size_t)bm * DM + (c + 1) * KC, DM, tid);
            fill_async<128, KC>(b + 2 * PL * 4, b + 3 * PL * 4,
                                W_H + (size_t)bn * DM + (c + 1) * KC,
                                W_L + (size_t)bn * DM + (c + 1) * KC, DM, tid);
            CPC();
            CPW(1);
        } else {
            CPW(0);
        }
        __syncthreads();
        uint32_t ba = sa + (c & 1) * BUF * 4;
        mma_chunk<4, 4, KC>(acc, ba, ba + PL * 4, ba + 2 * PL * 4, ba + 3 * PL * 4,
                            warp_m, warp_n, lane);
        __syncthreads();
    }

    const int lr = lane >> 2, lc = (lane & 3) * 2;
    #pragma unroll
    for (int mt = 0; mt < 4; mt++) {
        #pragma unroll
        for (int nt = 0; nt < 4; nt++) {
            int col = bn + warp_n + nt * 8 + lc;
            float b0 = bias[col], b1 = bias[col + 1];
            int h = col >> 6, dh = col & 63;
            #pragma unroll
            for (int half = 0; half < 2; half++) {
                int r = bm + warp_m + mt * 16 + lr + half * 8;
                float v0 = acc[mt][nt][half * 2 + 0] + b0;
                float v1 = acc[mt][nt][half * 2 + 1] + b1;
                int b = r >> 11, s = r & (S_LEN - 1);
                int bh = b * NH + h;
                uint32_t p0 = pack_split(v0), p1 = pack_split(v1);
                if (z == 2) {
                    size_t t0 = ((size_t)bh * DH + dh) * S_LEN + s;
                    size_t t1 = ((size_t)bh * DH + dh + 1) * S_LEN + s;
                    vH[t0] = (u16)p0; vL[t0] = (u16)(p0 >> 16);
                    vH[t1] = (u16)p1; vL[t1] = (u16)(p1 >> 16);
                } else {
                    u16* dH = (z == 0) ? qH : kH;
                    u16* dL = (z == 0) ? qL : kL;
                    size_t base = ((size_t)bh * S_LEN + s) * DH + dh;
                    *(uint32_t*)(dH + base) = (p0 & 0xFFFFu) | ((p1 & 0xFFFFu) << 16);
                    *(uint32_t*)(dL + base) = (p0 >> 16) | (p1 & 0xFFFF0000u);
                }
            }
        }
    }
}

// ===========================================================================
// Fused attention: scores + softmax + AV, two passes over K.
// Pass 1 (S only, M=0): hi-plane scores, 128-row K tiles.
// Pass 2: exact 3-MMA QK + 3-MMA PV, per-nt grouped (R15 ordering — measured
// faster here; 8-wide sweeps caused reg-pressure regression in R16).
// ===========================================================================
__global__ __launch_bounds__(256, 2)
void fused_attn(const u16* __restrict__ qH, const u16* __restrict__ qL,
                const u16* __restrict__ kH, const u16* __restrict__ kL,
                const u16* __restrict__ vH, const u16* __restrict__ vL,
                float* __restrict__ attn,
                u16* __restrict__ oH, u16* __restrict__ oL, float scale)
{
    constexpr int KSTR = 36;               // 64/2 + 4
    constexpr int QPL = 128 * KSTR;        // Q plane (u32)
    constexpr int TPL = 64 * KSTR;         // 64-row tile plane (u32)
    extern __shared__ uint32_t sm[];
    uint32_t sa = smem_u32(sm);
    const uint32_t kbase = sa;                      // K region: 4*TPL u32 (36KB)
    const uint32_t qvbase = sa + 4 * TPL * 4;       // Q planes / V ring (36KB)
    const uint32_t oQH = qvbase;
    const uint32_t oQL = qvbase + QPL * 4;
    const uint32_t vbase = qvbase;                  // V ring overlays Q

    const int bh = blockIdx.z;
    const int bb = bh >> 4, hh = bh & 15;
    const int tid = threadIdx.x, wid = tid >> 5, lane = tid & 31;
    const int bm = blockIdx.x * 128;
    const int wm = wid * 16;
    const size_t qoff = ((size_t)bh * S_LEN + bm) * DH;
    const u16* kbH = kH + (size_t)bh * S_LEN * DH;
    const u16* kbL = kL + (size_t)bh * S_LEN * DH;
    const u16* vbH = vH + (size_t)bh * DH * S_LEN;
    const u16* vbL = vL + (size_t)bh * DH * S_LEN;
    float* ab = attn + (size_t)bh * S_LEN * S_LEN;

    const int a_row = lane & 15;
    const int a_col = (lane >> 4) * 4;
    const int b_row = (lane & 7) + ((lane & 16) >> 1);
    const int b_col = (lane & 8) ? 4 : 0;
    const int lr = lane >> 2, lg = lane & 3;

    // prologue: Q (both planes) + K-hi tile 0 (128 rows)
    fill_async<128, 64>(oQH, oQL, qH + qoff, qL + qoff, DH, tid);
    fill_async1<128, 64>(kbase, kbH, DH, tid);
    CPC(); CPW(0);
    __syncthreads();

    // Q fragments: register-resident for both passes
    uint32_t qfh[4][4], qfl[4][4];
    #pragma unroll
    for (int ks = 0; ks < 4; ks++) {
        uint32_t off = ((wm + a_row) * KSTR + ks * 8 + a_col) * 4;
        LDSM_X4(qfh[ks][0], qfh[ks][1], qfh[ks][2], qfh[ks][3], oQH + off);
        LDSM_X4(qfl[ks][0], qfl[ks][1], qfl[ks][2], qfl[ks][3], oQL + off);
    }
    __syncthreads();   // Q region free after this point (V may overwrite)

    float S0 = 0.f, S1 = 0.f;

    // ---------------- pass 1: S only, 128-row K-hi tiles ----------------
    #pragma unroll 1
    for (int t = 0; t < 16; t++) {
        if (t + 1 < 16) {
            uint32_t kb = kbase + ((t + 1) & 1) * 2 * TPL * 4;
            fill_async1<128, 64>(kb, kbH + (size_t)(t + 1) * 128 * DH, DH, tid);
            CPC(); CPW(1);
        } else CPW(0);
        __syncthreads();

        uint32_t kh_ = kbase + (t & 1) * 2 * TPL * 4;
        #pragma unroll
        for (int half = 0; half < 2; half++) {
            float acc[8][4] = {};
            #pragma unroll
            for (int ks = 0; ks < 4; ks++) {
                uint32_t bhf[8][2];
                #pragma unroll
                for (int np = 0; np < 4; np++) {
                    uint32_t off = ((half * 64 + np * 16 + b_row) * KSTR + ks * 8 + b_col) * 4;
                    LDSM_X4(bhf[2*np][0], bhf[2*np][1], bhf[2*np+1][0], bhf[2*np+1][1], kh_ + off);
                }
                #pragma unroll
                for (int nt = 0; nt < 8; nt++)
                    mma16816(acc[nt], qfh[ks], bhf[nt][0], bhf[nt][1]);
            }
            float s0t = 0.f, s1t = 0.f;
            #pragma unroll
            for (int nt = 0; nt < 8; nt++) {
                s0t += __expf(acc[nt][0] * scale) + __expf(acc[nt][1] * scale);
                s1t += __expf(acc[nt][2] * scale) + __expf(acc[nt][3] * scale);
            }
            S0 += s0t;
            S1 += s1t;
        }
        __syncthreads();
    }
    S0 += __shfl_xor_sync(0xffffffffu, S0, 1);
    S0 += __shfl_xor_sync(0xffffffffu, S0, 2);
    S1 += __shfl_xor_sync(0xffffffffu, S1, 1);
    S1 += __shfl_xor_sync(0xffffffffu, S1, 2);
    const float inv0 = 1.0f / S0, inv1 = 1.0f / S1;

    // ---------------- pass 2: exact scores, attn write + P@V ----------------
    fill_async<64, 64>(kbase, kbase + TPL * 4, kbH, kbL, DH, tid);
    fill_async<64, 64>(vbase, vbase + TPL * 4, vbH, vbL, S_LEN, tid);
    CPC();

    float acco[8][4] = {};
    const int r0 = bm + wm + lr;
    const int r1 = r0 + 8;

    #pragma unroll 1
    for (int t = 0; t < 32; t++) {
        if (t + 1 < 32) {
            uint32_t kb = kbase + ((t + 1) & 1) * 2 * TPL * 4;
            uint32_t vb = vbase + ((t + 1) & 1) * 2 * TPL * 4;
            fill_async<64, 64>(kb, kb + TPL * 4,
                               kbH + (size_t)(t + 1) * 64 * DH,
                               kbL + (size_t)(t + 1) * 64 * DH, DH, tid);
            fill_async<64, 64>(vb, vb + TPL * 4,
                               vbH + (size_t)(t + 1) * 64,
                               vbL + (size_t)(t + 1) * 64, S_LEN, tid);
            CPC(); CPW(1);
        } else CPW(0);
        __syncthreads();

        uint32_t kh_ = kbase + (t & 1) * 2 * TPL * 4;
        uint32_t kl_ = kh_ + TPL * 4;
        float acc[8][4] = {};
        #pragma unroll
        for (int ks = 0; ks < 4; ks++) {
            uint32_t bhf[8][2], blf[8][2];
            #pragma unroll
            for (int np = 0; np < 4; np++) {
                uint32_t off = ((np * 16 + b_row) * KSTR + ks * 8 + b_col) * 4;
                LDSM_X4(bhf[2*np][0], bhf[2*np][1], bhf[2*np+1][0], bhf[2*np+1][1], kh_ + off);
                LDSM_X4(blf[2*np][0], blf[2*np][1], blf[2*np+1][0], blf[2*np+1][1], kl_ + off);
            }
            #pragma unroll
            for (int nt = 0; nt < 8; nt++) {
                mma16816(acc[nt], qfh[ks], bhf[nt][0], bhf[nt][1]);
                mma16816(acc[nt], qfh[ks], blf[nt][0], blf[nt][1]);
                mma16816(acc[nt], qfl[ks], bhf[nt][0], bhf[nt][1]);
            }
        }
        float pA[8][2], pB[8][2];
        #pragma unroll
        for (int nt = 0; nt < 8; nt++) {
            pA[nt][0] = __expf(acc[nt][0] * scale) * inv0;
            pA[nt][1] = __expf(acc[nt][1] * scale) * inv0;
            pB[nt][0] = __expf(acc[nt][2] * scale) * inv1;
            pB[nt][1] = __expf(acc[nt][3] * scale) * inv1;
            int col = t * 64 + nt * 8 + 2 * lg;
            stcs2(ab + (size_t)r0 * S_LEN + col, pA[nt][0], pA[nt][1]);
            stcs2(ab + (size_t)r1 * S_LEN + col, pB[nt][0], pB[nt][1]);
        }
        uint32_t vh_ = vbase + (t & 1) * 2 * TPL * 4;
        uint32_t vl_ = vh_ + TPL * 4;
        #pragma unroll
        for (int ks = 0; ks < 4; ks++) {
            uint32_t ah[4], al[4];
            pack_pair(pA[2*ks][0],   pA[2*ks][1],   ah[0], al[0]);
            pack_pair(pB[2*ks][0],   pB[2*ks][1],   ah[1], al[1]);
            pack_pair(pA[2*ks+1][0], pA[2*ks+1][1], ah[2], al[2]);
            pack_pair(pB[2*ks+1][0], pB[2*ks+1][1], ah[3], al[3]);
            uint32_t bhf[8][2], blf[8][2];
            #pragma unroll
            for (int np = 0; np < 4; np++) {
                uint32_t off = ((np * 16 + b_row) * KSTR + ks * 8 + b_col) * 4;
                LDSM_X4(bhf[2*np][0], bhf[2*np][1], bhf[2*np+1][0], bhf[2*np+1][1], vh_ + off);
                LDSM_X4(blf[2*np][0], blf[2*np][1], blf[2*np+1][0], blf[2*np+1][1], vl_ + off);
            }
            #pragma unroll
            for (int nt = 0; nt < 8; nt++) {
                mma16816(acco[nt], ah, bhf[nt][0], bhf[nt][1]);
                mma16816(acco[nt], ah, blf[nt][0], blf[nt][1]);
                mma16816(acco[nt], al, bhf[nt][0], bhf[nt][1]);
            }
        }
        __syncthreads();
    }

    // epilogue: o -> packed split planes, concat-head layout
    #pragma unroll
    for (int nt = 0; nt < 8; nt++) {
        int col = nt * 8 + 2 * lg;
        size_t base0 = ((size_t)bb * S_LEN + r0) * DM + hh * DH + col;
        size_t base1 = ((size_t)bb * S_LEN + r1) * DM + hh * DH + col;
        uint32_t h0, l0, h1, l1;
        pack_pair(acco[nt][0], acco[nt][1], h0, l0);
        pack_pair(acco[nt][2], acco[nt][3], h1, l1);
        *(uint32_t*)(oH + base0) = h0;
        *(uint32_t*)(oL + base0) = l0;
        *(uint32_t*)(oH + base1) = h1;
        *(uint32_t*)(oL + base1) = l1;
    }
}

// ===========================================================================
// Output projection: KC=32 double-buffered, 2 CTAs/SM, fp32 out.
// ===========================================================================
__global__ __launch_bounds__(256, 2)
void out_mma(const u16* __restrict__ aH, const u16* __restrict__ aL,
             const u16* __restrict__ wH, const u16* __restrict__ wL,
             const float* __restrict__ bo, float* __restrict__ out)
{
    constexpr int KC = 32, KSTR = KC / 2 + 4;
    constexpr int PL = 128 * KSTR;
    constexpr int BUF = 4 * PL;
    extern __shared__ uint32_t sm[];
    uint32_t sa = smem_u32(sm);

    const int tid = threadIdx.x;
    const int wid = tid >> 5, lane = tid & 31;
    const int bm = blockIdx.x * 128;
    const int bn = blockIdx.y * 128;
    const int warp_m = (wid >> 2) * 64;
    const int warp_n = (wid & 3) * 32;

    float acc[4][4][4] = {};

    fill_async<128, KC>(sa, sa + PL * 4, aH + (size_t)bm * DM, aL + (size_t)bm * DM, DM, tid);
    fill_async<128, KC>(sa + 2 * PL * 4, sa + 3 * PL * 4, wH + (size_t)bn * DM, wL + (size_t)bn * DM, DM, tid);
    CPC();

    #pragma unroll 1
    for (int c = 0; c < DM / KC; c++) {
        if (c + 1 < DM / KC) {
            uint32_t b = sa + ((c + 1) & 1) * BUF * 4;
            fill_async<128, KC>(b, b + PL * 4,
                                aH + (size_t)bm * DM + (c + 1) * KC,
                                aL + (size_t)bm * DM + (c + 1) * KC, DM, tid);
            fill_async<128, KC>(b + 2 * PL * 4, b + 3 * PL * 4,
                                wH + (size_t)bn * DM + (c + 1) * KC,
                                wL + (size_t)bn * DM + (c + 1) * KC, DM, tid);
            CPC();
            CPW(1);
        } else {
            CPW(0);
        }
        __syncthreads();
        uint32_t ba = sa + (c & 1) * BUF * 4;
        mma_chunk<4, 4, KC>(acc, ba, ba + PL * 4, ba + 2 * PL * 4, ba + 3 * PL * 4,
                            warp_m, warp_n, lane);
        __syncthreads();
    }

    const int lr = lane >> 2, lc = (lane & 3) * 2;
    #pragma unroll
    for (int mt = 0; mt < 4; mt++) {
        #pragma unroll
        for (int nt = 0; nt < 4; nt++) {
            int col = bn + warp_n + nt * 8 + lc;
            float b0 = bo[col], b1 = bo[col + 1];
            #pragma unroll
            for (int half = 0; half < 2; half++) {
                int r = bm + warp_m + mt * 16 + lr + half * 8;
                *(float2*)(out + (size_t)r * DM + col) =
                    make_float2(acc[mt][nt][half * 2 + 0] + b0,
                                acc[mt][nt][half * 2 + 1] + b1);
            }
        }
    }
}

// ===========================================================================
// Launch
// ===========================================================================
extern "C" void kernel_launch(void* const* d_in, const int* in_sizes, int n_in,
                              void* d_out, int out_size)
{
    const float* Q  = (const float*)d_in[0];
    const float* K  = (const float*)d_in[1];
    const float* V  = (const float*)d_in[2];
    const float* Wq = (const float*)d_in[3];
    const float* bq = (const float*)d_in[4];
    const float* Wk = (const float*)d_in[5];
    const float* bk = (const float*)d_in[6];
    const float* Wv = (const float*)d_in[7];
    const float* bv = (const float*)d_in[8];
    const float* Wo = (const float*)d_in[9];
    const float* bo = (const float*)d_in[10];

    float* out  = (float*)d_out;
    float* attn = out + OUT_ELEMS;

    u16 *inH, *inL, *wH, *wL, *qH, *qL, *kH, *kL, *vH, *vL, *oH, *oL;
    cudaGetSymbolAddress((void**)&inH, g_inH);
    cudaGetSymbolAddress((void**)&inL, g_inL);
    cudaGetSymbolAddress((void**)&wH, g_wH);
    cudaGetSymbolAddress((void**)&wL, g_wL);
    cudaGetSymbolAddress((void**)&qH, g_qH);
    cudaGetSymbolAddress((void**)&qL, g_qL);
    cudaGetSymbolAddress((void**)&kH, g_kH);
    cudaGetSymbolAddress((void**)&kL, g_kL);
    cudaGetSymbolAddress((void**)&vH, g_vH);
    cudaGetSymbolAddress((void**)&vL, g_vL);
    cudaGetSymbolAddress((void**)&oH, g_oH);
    cudaGetSymbolAddress((void**)&oL, g_oL);

    const int KSTR32 = 32 / 2 + 4;                            // 20
    const int SM_PROJ = 2 * 4 * 128 * KSTR32 * 4;             // 81920
    const int SM_FA   = (4 * 64 + 2 * 128) * 36 * 4;          // 73728
    cudaFuncSetAttribute(proj_mma, cudaFuncAttributeMaxDynamicSharedMemorySize, SM_PROJ);
    cudaFuncSetAttribute(out_mma, cudaFuncAttributeMaxDynamicSharedMemorySize, SM_PROJ);
    cudaFuncSetAttribute(fused_attn, cudaFuncAttributeMaxDynamicSharedMemorySize, SM_FA);

    convert_in<<<dim3(M_ROWS * DM / 8 / 256, 3), 256>>>(Q, K, V, inH, inL);
    convert_w<<<dim3(DM / 64, DM / 64, 4), 256>>>(Wq, Wk, Wv, Wo, wH, wL);

    proj_mma<<<dim3(M_ROWS / 128, DM / 128, 3), 256, SM_PROJ>>>(
        inH, inL, wH, wL, bq, bk, bv, qH, qL, kH, kL, vH, vL);

    fused_attn<<<dim3(S_LEN / 128, 1, BH), 256, SM_FA>>>(
        qH, qL, kH, kL, vH, vL, attn, oH, oL, 0.125f);

    out_mma<<<dim3(M_ROWS / 128, DM / 128), 256, SM_PROJ>>>(
        oH, oL, wH + 3 * (size_t)(DM * DM), wL + 3 * (size_t)(DM * DM), bo, out);
}